// round 9
// baseline (speedup 1.0000x reference)
#include <cuda_runtime.h>
#include <cuda_fp16.h>

#define N_NODES 100000
#define MAX_E   1600000
#define FDIM    64
#define NCHUNK  ((N_NODES + 255) / 256)      // 391 scan chunks

// ---- scratch (device globals referenced directly by kernels) ----
__device__ int    d_mode;                    // 1 = edge_index is int64, 0 = int32
__device__ int    d_deg[N_NODES];            // in-degree (real edges only)
__device__ int    d_rowstart[N_NODES];       // CSR row offsets (exclusive scan)
__device__ int    d_cursor[N_NODES];         // scatter cursors
__device__ float  d_dinv[N_NODES];           // (1+deg)^{-1/2}
__device__ int2   d_ed[MAX_E];               // packed (src, dst)
__device__ int    d_srcSorted[MAX_E];        // src indices grouped by dst
__device__ int    d_chunksum[512];           // per-chunk scan sums
__device__ uint4  d_gh[N_NODES * 8];         // dinv-scaled linear output, fp16 (128B/row)
__device__ float4 d_h[N_NODES * (FDIM / 4)]; // hidden activations (fp32)

// zero degrees; block 0 also detects edge_index dtype (int64 LE values < 2^32
// have all odd int32 words zero; int32 node ids make that vanishingly unlikely)
__global__ void k_init(const int* __restrict__ ei32) {
    int i = blockIdx.x * blockDim.x + threadIdx.x;
    if (i < N_NODES) d_deg[i] = 0;
    if (blockIdx.x == 0 && threadIdx.x < 32) {
        int nz = 0;
        for (int k = threadIdx.x; k < 512; k += 32)
            if (ei32[2 * k + 1] != 0) nz = 1;
        nz = __any_sync(0xffffffffu, nz);
        if (threadIdx.x == 0) d_mode = nz ? 0 : 1;
    }
}

// decode edges (either dtype) -> packed int2, count in-degree
__global__ void k_edge(const int* __restrict__ ei, int E) {
    int e = blockIdx.x * blockDim.x + threadIdx.x;
    if (e >= E) return;
    int s, d;
    if (d_mode) {                 // int64: take low word of element e / E+e
        s = ei[2 * e];
        d = ei[2 * (E + e)];
    } else {                      // int32
        s = ei[e];
        d = ei[E + e];
    }
    if ((unsigned)s >= (unsigned)N_NODES) s = 0;   // safety clamp
    if ((unsigned)d >= (unsigned)N_NODES) d = 0;
    d_ed[e] = make_int2(s, d);
    atomicAdd(&d_deg[d], 1);
}

// phase 1: per-256-chunk exclusive scan of deg (warp-shuffle), chunk totals out
__global__ void k_scan1() {
    __shared__ int wsum[8];
    int i = threadIdx.x;
    int gi = blockIdx.x * 256 + i;
    int v = (gi < N_NODES) ? d_deg[gi] : 0;
    int lane = i & 31, w = i >> 5;
    int x = v;
    #pragma unroll
    for (int off = 1; off < 32; off <<= 1) {
        int t = __shfl_up_sync(0xffffffffu, x, off);
        if (lane >= off) x += t;
    }
    if (lane == 31) wsum[w] = x;
    __syncthreads();
    if (w == 0) {
        int s = (lane < 8) ? wsum[lane] : 0;
        #pragma unroll
        for (int off = 1; off < 8; off <<= 1) {
            int t = __shfl_up_sync(0xffffffffu, s, off);
            if (lane >= off) s += t;
        }
        if (lane < 8) wsum[lane] = s;
    }
    __syncthreads();
    int excl = x - v + (w > 0 ? wsum[w - 1] : 0);
    if (gi < N_NODES) d_rowstart[gi] = excl;
    if (i == 255) d_chunksum[blockIdx.x] = wsum[7];
}

// fused phases 2+3: each block reduces chunksums below it (L2-hot, <=391 ints),
// then finalizes rowstart, cursors, dinv for its 256 nodes
__global__ void k_scan23() {
    __shared__ int red[256];
    int b = blockIdx.x;
    int t = threadIdx.x;
    int partial = 0;
    for (int i = t; i < b; i += 256) partial += d_chunksum[i];
    red[t] = partial;
    __syncthreads();
    #pragma unroll
    for (int off = 128; off > 0; off >>= 1) {
        if (t < off) red[t] += red[t + off];
        __syncthreads();
    }
    int base = red[0];
    int gi = b * 256 + t;
    if (gi < N_NODES) {
        int rs = d_rowstart[gi] + base;
        d_rowstart[gi] = rs;
        d_cursor[gi] = rs;
        d_dinv[gi] = rsqrtf(1.0f + (float)d_deg[gi]);
    }
}

// bucket src indices by dst (order within bucket irrelevant for a sum)
__global__ void k_scatter(int E) {
    int e = blockIdx.x * blockDim.x + threadIdx.x;
    if (e >= E) return;
    int2 sd = d_ed[e];
    int pos = atomicAdd(&d_cursor[sd.y], 1);
    d_srcSorted[pos] = sd.x;
}

// g[row] = fp16( (A[row] @ W) * dinv[row] );  M x 64 @ 64 x 64
// 64 threads per block, 64x64 tile, 8x8 register tile (16 FMA per LDS.128)
__global__ __launch_bounds__(64) void k_gemm(
    const float* __restrict__ A_ext, const float* __restrict__ W,
    int M, int src_sel) {
    __shared__ float As[64][68];   // k-major: As[k][row]
    __shared__ float Ws[64][68];   // k-major: Ws[k][col]
    const int t = threadIdx.x;     // 0..63
    const int block_row = blockIdx.x * 64;
    const float4* A4 = src_sel ? (const float4*)d_h : (const float4*)A_ext;

    // load W (row-major [k][col]) into Ws: 1024 float4s, 16 per thread
    #pragma unroll
    for (int r = 0; r < 16; r++) {
        int p = t + r * 64;
        int k = p >> 4;
        int c4 = p & 15;
        float4 w = ((const float4*)W)[p];
        *(float4*)&Ws[k][c4 * 4] = w;
    }
    // load A tile transposed into As[k][row]: 1024 float4s, 16 per thread
    #pragma unroll
    for (int r = 0; r < 16; r++) {
        int p = t + r * 64;
        int row = p >> 4;
        int k4 = p & 15;
        int grow = block_row + row;
        float4 a = (grow < M) ? A4[grow * 16 + k4]
                              : make_float4(0.f, 0.f, 0.f, 0.f);
        As[k4 * 4 + 0][row] = a.x;
        As[k4 * 4 + 1][row] = a.y;
        As[k4 * 4 + 2][row] = a.z;
        As[k4 * 4 + 3][row] = a.w;
    }
    __syncthreads();

    const int tx = t & 7;    // col group (8 cols)
    const int ty = t >> 3;   // row group (8 rows)
    float acc[8][8] = {};
    #pragma unroll
    for (int k = 0; k < 64; k++) {
        float av[8], bv[8];
        *(float4*)&av[0] = *(const float4*)&As[k][ty * 8 + 0];
        *(float4*)&av[4] = *(const float4*)&As[k][ty * 8 + 4];
        *(float4*)&bv[0] = *(const float4*)&Ws[k][tx * 8 + 0];
        *(float4*)&bv[4] = *(const float4*)&Ws[k][tx * 8 + 4];
        #pragma unroll
        for (int i = 0; i < 8; i++)
            #pragma unroll
            for (int j = 0; j < 8; j++)
                acc[i][j] += av[i] * bv[j];
    }
    #pragma unroll
    for (int i = 0; i < 8; i++) {
        int grow = block_row + ty * 8 + i;
        if (grow < M) {
            float sc = d_dinv[grow];
            __half2 h0 = __floats2half2_rn(acc[i][0] * sc, acc[i][1] * sc);
            __half2 h1 = __floats2half2_rn(acc[i][2] * sc, acc[i][3] * sc);
            __half2 h2 = __floats2half2_rn(acc[i][4] * sc, acc[i][5] * sc);
            __half2 h3 = __floats2half2_rn(acc[i][6] * sc, acc[i][7] * sc);
            uint4 u;
            u.x = *(unsigned int*)&h0;
            u.y = *(unsigned int*)&h1;
            u.z = *(unsigned int*)&h2;
            u.w = *(unsigned int*)&h3;
            d_gh[grow * 8 + tx] = u;
        }
    }
}

__device__ __forceinline__ void acc8(uint4 v, float* a) {
    float2 f0 = __half22float2(*(__half2*)&v.x);
    float2 f1 = __half22float2(*(__half2*)&v.y);
    float2 f2 = __half22float2(*(__half2*)&v.z);
    float2 f3 = __half22float2(*(__half2*)&v.w);
    a[0] += f0.x; a[1] += f0.y; a[2] += f1.x; a[3] += f1.y;
    a[4] += f2.x; a[5] += f2.y; a[6] += f3.x; a[7] += f3.y;
}

// fused aggregation + epilogue: 8 threads per dst node, fp16 gather-reduce,
// out[d] = [relu]( dinv[d] * (sum_{e: dst=d} g[src_e] + g[d]) + b )
// dst_sel: 1 -> write d_h (fp32) with relu ; 0 -> write external out (fp32)
__global__ void k_gat(const float* __restrict__ b, float4* __restrict__ out_ext,
                      int dst_sel) {
    const uint4* __restrict__ g   = d_gh;
    const int*   __restrict__ srt = d_srcSorted;

    int t = blockIdx.x * blockDim.x + threadIdx.x;
    int node = t >> 3;
    if (node >= N_NODES) return;
    int c = t & 7;                          // 8 halves (16B) per thread

    float acc[8] = {};
    acc8(g[node * 8 + c], acc);             // self loop (already dinv-scaled)
    int start = d_rowstart[node];
    int cnt = d_deg[node];

    int j = 0;
    for (; j + 4 <= cnt; j += 4) {          // 4-wide: batch loads for MLP
        int s0 = srt[start + j + 0];
        int s1 = srt[start + j + 1];
        int s2 = srt[start + j + 2];
        int s3 = srt[start + j + 3];
        uint4 v0 = g[s0 * 8 + c];
        uint4 v1 = g[s1 * 8 + c];
        uint4 v2 = g[s2 * 8 + c];
        uint4 v3 = g[s3 * 8 + c];
        acc8(v0, acc); acc8(v1, acc); acc8(v2, acc); acc8(v3, acc);
    }
    for (; j < cnt; j++) {
        int si = srt[start + j];
        acc8(g[si * 8 + c], acc);
    }

    float dv = d_dinv[node];
    float4 b0 = ((const float4*)b)[c * 2 + 0];
    float4 b1 = ((const float4*)b)[c * 2 + 1];
    float4 o0, o1;
    o0.x = fmaf(dv, acc[0], b0.x); o0.y = fmaf(dv, acc[1], b0.y);
    o0.z = fmaf(dv, acc[2], b0.z); o0.w = fmaf(dv, acc[3], b0.w);
    o1.x = fmaf(dv, acc[4], b1.x); o1.y = fmaf(dv, acc[5], b1.y);
    o1.z = fmaf(dv, acc[6], b1.z); o1.w = fmaf(dv, acc[7], b1.w);
    if (dst_sel) {
        o0.x = fmaxf(o0.x, 0.f); o0.y = fmaxf(o0.y, 0.f);
        o0.z = fmaxf(o0.z, 0.f); o0.w = fmaxf(o0.w, 0.f);
        o1.x = fmaxf(o1.x, 0.f); o1.y = fmaxf(o1.y, 0.f);
        o1.z = fmaxf(o1.z, 0.f); o1.w = fmaxf(o1.w, 0.f);
        d_h[node * 16 + c * 2 + 0] = o0;
        d_h[node * 16 + c * 2 + 1] = o1;
    } else {
        out_ext[node * 16 + c * 2 + 0] = o0;
        out_ext[node * 16 + c * 2 + 1] = o1;
    }
}

extern "C" void kernel_launch(void* const* d_in, const int* in_sizes, int n_in,
                              void* d_out, int out_size) {
    const float* x  = (const float*)d_in[0];
    const int*   ei = (const int*)d_in[1];     // int32 view; int64 handled via d_mode
    const float* W1 = (const float*)d_in[2];
    const float* b1 = (const float*)d_in[3];
    const float* W2 = (const float*)d_in[4];
    const float* b2 = (const float*)d_in[5];
    const int E = in_sizes[1] / 2;             // elements of edge_index / 2

    const int TPB = 256;
    const int gridN    = (N_NODES + TPB - 1) / TPB;      // 391
    const int gridE    = (E + TPB - 1) / TPB;
    const int gridGat  = (N_NODES * 8 + TPB - 1) / TPB;  // 3125
    const int gridGemm = (N_NODES + 63) / 64;            // 1563

    // ---- CSR build (per run) ----
    k_init<<<gridN, TPB>>>(ei);
    k_edge<<<gridE, TPB>>>(ei, E);
    k_scan1<<<NCHUNK, 256>>>();
    k_scan23<<<NCHUNK, 256>>>();
    k_scatter<<<gridE, TPB>>>(E);

    // ---- layer 1 ----
    k_gemm<<<gridGemm, 64>>>(x, W1, N_NODES, 0);
    k_gat<<<gridGat, TPB>>>(b1, nullptr, 1);

    // ---- layer 2 ----
    k_gemm<<<gridGemm, 64>>>(nullptr, W2, N_NODES, 1);
    k_gat<<<gridGat, TPB>>>(b2, (float4*)d_out, 0);
}

// round 10
// speedup vs baseline: 1.0492x; 1.0492x over previous
#include <cuda_runtime.h>
#include <cuda_fp16.h>

#define N_NODES 100000
#define MAX_E   1600000
#define FDIM    64
#define NCHUNK  ((N_NODES + 255) / 256)      // 391 scan chunks

#define GEMM_MTILE 256
#define AS_PAD     260                       // 256 rows + 4 pad
#define WS_PAD     68                        // 64 cols + 4 pad
#define GEMM_SMEM  ((64 * AS_PAD + 64 * WS_PAD) * 4)   // 83968 B

// ---- scratch (device globals referenced directly by kernels) ----
__device__ int    d_mode;                    // 1 = edge_index is int64, 0 = int32
__device__ int    d_deg[N_NODES];            // in-degree (real edges only)
__device__ int    d_rowstart[N_NODES];       // CSR row offsets (exclusive scan)
__device__ int    d_cursor[N_NODES];         // scatter cursors
__device__ float  d_dinv[N_NODES];           // (1+deg)^{-1/2}
__device__ int2   d_ed[MAX_E];               // packed (src, dst)
__device__ int    d_srcSorted[MAX_E];        // src indices grouped by dst
__device__ int    d_chunksum[512];           // per-chunk scan sums
__device__ uint4  d_gh[N_NODES * 8];         // dinv-scaled linear output, fp16 (128B/row)
__device__ float4 d_h[N_NODES * (FDIM / 4)]; // hidden activations (fp32)

// zero degrees; block 0 also detects edge_index dtype (int64 LE values < 2^32
// have all odd int32 words zero; int32 node ids make that vanishingly unlikely)
__global__ void k_init(const int* __restrict__ ei32) {
    int i = blockIdx.x * blockDim.x + threadIdx.x;
    if (i < N_NODES) d_deg[i] = 0;
    if (blockIdx.x == 0 && threadIdx.x < 32) {
        int nz = 0;
        for (int k = threadIdx.x; k < 512; k += 32)
            if (ei32[2 * k + 1] != 0) nz = 1;
        nz = __any_sync(0xffffffffu, nz);
        if (threadIdx.x == 0) d_mode = nz ? 0 : 1;
    }
}

// decode edges (either dtype) -> packed int2, count in-degree
__global__ void k_edge(const int* __restrict__ ei, int E) {
    int e = blockIdx.x * blockDim.x + threadIdx.x;
    if (e >= E) return;
    int s, d;
    if (d_mode) {                 // int64: take low word of element e / E+e
        s = ei[2 * e];
        d = ei[2 * (E + e)];
    } else {                      // int32
        s = ei[e];
        d = ei[E + e];
    }
    if ((unsigned)s >= (unsigned)N_NODES) s = 0;   // safety clamp
    if ((unsigned)d >= (unsigned)N_NODES) d = 0;
    d_ed[e] = make_int2(s, d);
    atomicAdd(&d_deg[d], 1);
}

// phase 1: per-256-chunk exclusive scan of deg (warp-shuffle), chunk totals out
__global__ void k_scan1() {
    __shared__ int wsum[8];
    int i = threadIdx.x;
    int gi = blockIdx.x * 256 + i;
    int v = (gi < N_NODES) ? d_deg[gi] : 0;
    int lane = i & 31, w = i >> 5;
    int x = v;
    #pragma unroll
    for (int off = 1; off < 32; off <<= 1) {
        int t = __shfl_up_sync(0xffffffffu, x, off);
        if (lane >= off) x += t;
    }
    if (lane == 31) wsum[w] = x;
    __syncthreads();
    if (w == 0) {
        int s = (lane < 8) ? wsum[lane] : 0;
        #pragma unroll
        for (int off = 1; off < 8; off <<= 1) {
            int t = __shfl_up_sync(0xffffffffu, s, off);
            if (lane >= off) s += t;
        }
        if (lane < 8) wsum[lane] = s;
    }
    __syncthreads();
    int excl = x - v + (w > 0 ? wsum[w - 1] : 0);
    if (gi < N_NODES) d_rowstart[gi] = excl;
    if (i == 255) d_chunksum[blockIdx.x] = wsum[7];
}

// fused phases 2+3: each block reduces chunksums below it (L2-hot, <=391 ints),
// then finalizes rowstart, cursors, dinv for its 256 nodes
__global__ void k_scan23() {
    __shared__ int red[256];
    int b = blockIdx.x;
    int t = threadIdx.x;
    int partial = 0;
    for (int i = t; i < b; i += 256) partial += d_chunksum[i];
    red[t] = partial;
    __syncthreads();
    #pragma unroll
    for (int off = 128; off > 0; off >>= 1) {
        if (t < off) red[t] += red[t + off];
        __syncthreads();
    }
    int base = red[0];
    int gi = b * 256 + t;
    if (gi < N_NODES) {
        int rs = d_rowstart[gi] + base;
        d_rowstart[gi] = rs;
        d_cursor[gi] = rs;
        d_dinv[gi] = rsqrtf(1.0f + (float)d_deg[gi]);
    }
}

// bucket src indices by dst (order within bucket irrelevant for a sum)
__global__ void k_scatter(int E) {
    int e = blockIdx.x * blockDim.x + threadIdx.x;
    if (e >= E) return;
    int2 sd = d_ed[e];
    int pos = atomicAdd(&d_cursor[sd.y], 1);
    d_srcSorted[pos] = sd.x;
}

// g[row] = fp16( (A[row] @ W) * dinv[row] );  M x 64 @ 64 x 64
// 256 threads, 256x64 tile, 8x8 register tile (2x LDS.128 per 32 FMA)
__global__ __launch_bounds__(256) void k_gemm(
    const float* __restrict__ A_ext, const float* __restrict__ W,
    int M, int src_sel) {
    extern __shared__ float sm[];
    float (*As)[AS_PAD] = (float(*)[AS_PAD])sm;              // [64 k][256 row]
    float (*Ws)[WS_PAD] = (float(*)[WS_PAD])(sm + 64 * AS_PAD); // [64 k][64 col]
    const int t = threadIdx.x;
    const int block_row = blockIdx.x * GEMM_MTILE;
    const float4* A4 = src_sel ? (const float4*)d_h : (const float4*)A_ext;

    // load W (row-major [k][col]) into Ws: 1024 float4s, 4 per thread
    #pragma unroll
    for (int r = 0; r < 4; r++) {
        int p = t + r * 256;
        int k = p >> 4;
        int c4 = p & 15;
        float4 w = ((const float4*)W)[p];
        *(float4*)&Ws[k][c4 * 4] = w;
    }
    // load A tile (256 rows) transposed into As[k][row]: 4096 float4s, 16/thread
    #pragma unroll
    for (int r = 0; r < 16; r++) {
        int p = t + r * 256;
        int row = p >> 4;
        int k4 = p & 15;
        int grow = block_row + row;
        float4 a = (grow < M) ? A4[grow * 16 + k4]
                              : make_float4(0.f, 0.f, 0.f, 0.f);
        As[k4 * 4 + 0][row] = a.x;
        As[k4 * 4 + 1][row] = a.y;
        As[k4 * 4 + 2][row] = a.z;
        As[k4 * 4 + 3][row] = a.w;
    }
    __syncthreads();

    const int tx = t & 7;    // col group (8 cols)
    const int ty = t >> 3;   // row group (32 groups x 8 rows)
    float acc[8][8] = {};
    #pragma unroll
    for (int k = 0; k < 64; k++) {
        float av[8], bv[8];
        *(float4*)&av[0] = *(const float4*)&As[k][ty * 8 + 0];
        *(float4*)&av[4] = *(const float4*)&As[k][ty * 8 + 4];
        *(float4*)&bv[0] = *(const float4*)&Ws[k][tx * 8 + 0];
        *(float4*)&bv[4] = *(const float4*)&Ws[k][tx * 8 + 4];
        #pragma unroll
        for (int i = 0; i < 8; i++)
            #pragma unroll
            for (int j = 0; j < 8; j++)
                acc[i][j] += av[i] * bv[j];
    }
    #pragma unroll
    for (int i = 0; i < 8; i++) {
        int grow = block_row + ty * 8 + i;
        if (grow < M) {
            float sc = d_dinv[grow];
            __half2 h0 = __floats2half2_rn(acc[i][0] * sc, acc[i][1] * sc);
            __half2 h1 = __floats2half2_rn(acc[i][2] * sc, acc[i][3] * sc);
            __half2 h2 = __floats2half2_rn(acc[i][4] * sc, acc[i][5] * sc);
            __half2 h3 = __floats2half2_rn(acc[i][6] * sc, acc[i][7] * sc);
            uint4 u;
            u.x = *(unsigned int*)&h0;
            u.y = *(unsigned int*)&h1;
            u.z = *(unsigned int*)&h2;
            u.w = *(unsigned int*)&h3;
            d_gh[grow * 8 + tx] = u;
        }
    }
}

__device__ __forceinline__ void acc8(uint4 v, float* a) {
    float2 f0 = __half22float2(*(__half2*)&v.x);
    float2 f1 = __half22float2(*(__half2*)&v.y);
    float2 f2 = __half22float2(*(__half2*)&v.z);
    float2 f3 = __half22float2(*(__half2*)&v.w);
    a[0] += f0.x; a[1] += f0.y; a[2] += f1.x; a[3] += f1.y;
    a[4] += f2.x; a[5] += f2.y; a[6] += f3.x; a[7] += f3.y;
}

// fused aggregation + epilogue: 8 threads per dst node, fp16 gather-reduce,
// out[d] = [relu]( dinv[d] * (sum_{e: dst=d} g[src_e] + g[d]) + b )
// dst_sel: 1 -> write d_h (fp32) with relu ; 0 -> write external out (fp32)
__global__ void k_gat(const float* __restrict__ b, float4* __restrict__ out_ext,
                      int dst_sel) {
    const uint4* __restrict__ g   = d_gh;
    const int*   __restrict__ srt = d_srcSorted;

    int t = blockIdx.x * blockDim.x + threadIdx.x;
    int node = t >> 3;
    if (node >= N_NODES) return;
    int c = t & 7;                          // 8 halves (16B) per thread

    float acc[8] = {};
    acc8(g[node * 8 + c], acc);             // self loop (already dinv-scaled)
    int start = d_rowstart[node];
    int cnt = d_deg[node];

    int j = 0;
    for (; j + 4 <= cnt; j += 4) {          // 4-wide: batch loads for MLP
        int s0 = srt[start + j + 0];
        int s1 = srt[start + j + 1];
        int s2 = srt[start + j + 2];
        int s3 = srt[start + j + 3];
        uint4 v0 = g[s0 * 8 + c];
        uint4 v1 = g[s1 * 8 + c];
        uint4 v2 = g[s2 * 8 + c];
        uint4 v3 = g[s3 * 8 + c];
        acc8(v0, acc); acc8(v1, acc); acc8(v2, acc); acc8(v3, acc);
    }
    for (; j < cnt; j++) {
        int si = srt[start + j];
        acc8(g[si * 8 + c], acc);
    }

    float dv = d_dinv[node];
    float4 b0 = ((const float4*)b)[c * 2 + 0];
    float4 b1 = ((const float4*)b)[c * 2 + 1];
    float4 o0, o1;
    o0.x = fmaf(dv, acc[0], b0.x); o0.y = fmaf(dv, acc[1], b0.y);
    o0.z = fmaf(dv, acc[2], b0.z); o0.w = fmaf(dv, acc[3], b0.w);
    o1.x = fmaf(dv, acc[4], b1.x); o1.y = fmaf(dv, acc[5], b1.y);
    o1.z = fmaf(dv, acc[6], b1.z); o1.w = fmaf(dv, acc[7], b1.w);
    if (dst_sel) {
        o0.x = fmaxf(o0.x, 0.f); o0.y = fmaxf(o0.y, 0.f);
        o0.z = fmaxf(o0.z, 0.f); o0.w = fmaxf(o0.w, 0.f);
        o1.x = fmaxf(o1.x, 0.f); o1.y = fmaxf(o1.y, 0.f);
        o1.z = fmaxf(o1.z, 0.f); o1.w = fmaxf(o1.w, 0.f);
        d_h[node * 16 + c * 2 + 0] = o0;
        d_h[node * 16 + c * 2 + 1] = o1;
    } else {
        out_ext[node * 16 + c * 2 + 0] = o0;
        out_ext[node * 16 + c * 2 + 1] = o1;
    }
}

extern "C" void kernel_launch(void* const* d_in, const int* in_sizes, int n_in,
                              void* d_out, int out_size) {
    const float* x  = (const float*)d_in[0];
    const int*   ei = (const int*)d_in[1];     // int32 view; int64 handled via d_mode
    const float* W1 = (const float*)d_in[2];
    const float* b1 = (const float*)d_in[3];
    const float* W2 = (const float*)d_in[4];
    const float* b2 = (const float*)d_in[5];
    const int E = in_sizes[1] / 2;             // elements of edge_index / 2

    // allow >48KB dynamic smem for the GEMM (idempotent attribute set)
    cudaFuncSetAttribute(k_gemm, cudaFuncAttributeMaxDynamicSharedMemorySize,
                         GEMM_SMEM);

    const int TPB = 256;
    const int gridN    = (N_NODES + TPB - 1) / TPB;             // 391
    const int gridE    = (E + TPB - 1) / TPB;
    const int gridGat  = (N_NODES * 8 + TPB - 1) / TPB;         // 3125
    const int gridGemm = (N_NODES + GEMM_MTILE - 1) / GEMM_MTILE; // 391

    // ---- CSR build (per run) ----
    k_init<<<gridN, TPB>>>(ei);
    k_edge<<<gridE, TPB>>>(ei, E);
    k_scan1<<<NCHUNK, 256>>>();
    k_scan23<<<NCHUNK, 256>>>();
    k_scatter<<<gridE, TPB>>>(E);

    // ---- layer 1 ----
    k_gemm<<<gridGemm, TPB, GEMM_SMEM>>>(x, W1, N_NODES, 0);
    k_gat<<<gridGat, TPB>>>(b1, nullptr, 1);

    // ---- layer 2 ----
    k_gemm<<<gridGemm, TPB, GEMM_SMEM>>>(nullptr, W2, N_NODES, 1);
    k_gat<<<gridGat, TPB>>>(b2, (float4*)d_out, 0);
}

// round 12
// speedup vs baseline: 1.0527x; 1.0033x over previous
#include <cuda_runtime.h>
#include <cuda_fp16.h>

#define N_NODES 100000
#define MAX_E   1600000
#define FDIM    64
#define NCHUNK  ((N_NODES + 255) / 256)      // 391 scan chunks

#define GEMM_MTILE 256
#define AS_PAD     260                       // 256 rows + 4 pad
#define WS_PAD     68                        // 64 cols + 4 pad
#define GEMM_SMEM  ((64 * AS_PAD + 64 * WS_PAD) * 4)   // 83968 B

// ---- scratch (device globals referenced directly by kernels) ----
// d_deg is zero at module load and re-zeroed by layer-2 k_gat each run, so
// every graph replay sees a clean state without a dedicated init kernel.
__device__ int    d_deg[N_NODES];            // in-degree (real edges only)
__device__ int    d_rowstart[N_NODES];       // CSR row offsets (exclusive scan)
__device__ int    d_cursor[N_NODES];         // scatter cursors
__device__ float  d_dinv[N_NODES];           // (1+deg)^{-1/2}
__device__ int    d_srcSorted[MAX_E];        // src indices grouped by dst
__device__ int    d_chunksum[512];           // per-chunk scan sums
__device__ uint4  d_gh[N_NODES * 8];         // dinv-scaled linear output, fp16 (128B/row)
__device__ float4 d_h[N_NODES * (FDIM / 4)]; // hidden activations (fp32)

// per-block edge dtype probe: int64 LE values < 2^32 have all odd int32 words
// zero over the first 512 words; int32 node ids make that vanishingly unlikely.
__device__ __forceinline__ int probe_mode64(const int* __restrict__ ei) {
    int t = threadIdx.x;
    int v = (t < 256) ? ei[2 * t + 1] : 0;
    return !__syncthreads_or(v != 0);        // 1 = int64, 0 = int32
}

__device__ __forceinline__ void decode_edge(const int* __restrict__ ei, int E,
                                            int mode64, int e, int& s, int& d) {
    if (mode64) { s = ei[2 * e]; d = ei[2 * (E + e)]; }
    else        { s = ei[e];     d = ei[E + e]; }
    if ((unsigned)s >= (unsigned)N_NODES) s = 0;   // safety clamp
    if ((unsigned)d >= (unsigned)N_NODES) d = 0;
}

// count in-degree (deg assumed zero on entry)
__global__ void k_edge(const int* __restrict__ ei, int E) {
    int mode64 = probe_mode64(ei);
    int e = blockIdx.x * blockDim.x + threadIdx.x;
    if (e >= E) return;
    int s, d;
    decode_edge(ei, E, mode64, e, s, d);
    atomicAdd(&d_deg[d], 1);
}

// phase 1: per-256-chunk exclusive scan of deg (warp-shuffle), chunk totals out
__global__ void k_scan1() {
    __shared__ int wsum[8];
    int i = threadIdx.x;
    int gi = blockIdx.x * 256 + i;
    int v = (gi < N_NODES) ? d_deg[gi] : 0;
    int lane = i & 31, w = i >> 5;
    int x = v;
    #pragma unroll
    for (int off = 1; off < 32; off <<= 1) {
        int t = __shfl_up_sync(0xffffffffu, x, off);
        if (lane >= off) x += t;
    }
    if (lane == 31) wsum[w] = x;
    __syncthreads();
    if (w == 0) {
        int s = (lane < 8) ? wsum[lane] : 0;
        #pragma unroll
        for (int off = 1; off < 8; off <<= 1) {
            int t = __shfl_up_sync(0xffffffffu, s, off);
            if (lane >= off) s += t;
        }
        if (lane < 8) wsum[lane] = s;
    }
    __syncthreads();
    int excl = x - v + (w > 0 ? wsum[w - 1] : 0);
    if (gi < N_NODES) d_rowstart[gi] = excl;
    if (i == 255) d_chunksum[blockIdx.x] = wsum[7];
}

// fused phases 2+3: each block reduces chunksums below it (L2-hot, <=391 ints),
// then finalizes rowstart, cursors, dinv for its 256 nodes
__global__ void k_scan23() {
    __shared__ int red[256];
    int b = blockIdx.x;
    int t = threadIdx.x;
    int partial = 0;
    for (int i = t; i < b; i += 256) partial += d_chunksum[i];
    red[t] = partial;
    __syncthreads();
    #pragma unroll
    for (int off = 128; off > 0; off >>= 1) {
        if (t < off) red[t] += red[t + off];
        __syncthreads();
    }
    int base = red[0];
    int gi = b * 256 + t;
    if (gi < N_NODES) {
        int rs = d_rowstart[gi] + base;
        d_rowstart[gi] = rs;
        d_cursor[gi] = rs;
        d_dinv[gi] = rsqrtf(1.0f + (float)d_deg[gi]);
    }
}

// bucket src indices by dst, decoding edge_index directly
__global__ void k_scatter(const int* __restrict__ ei, int E) {
    int mode64 = probe_mode64(ei);
    int e = blockIdx.x * blockDim.x + threadIdx.x;
    if (e >= E) return;
    int s, d;
    decode_edge(ei, E, mode64, e, s, d);
    int pos = atomicAdd(&d_cursor[d], 1);
    d_srcSorted[pos] = s;
}

// g[row] = fp16( (A[row] @ W) * dinv[row] );  M x 64 @ 64 x 64
// 256 threads, 256x64 tile, 8x8 register tile
__global__ __launch_bounds__(256) void k_gemm(
    const float* __restrict__ A_ext, const float* __restrict__ W,
    int M, int src_sel) {
    extern __shared__ float sm[];
    float (*As)[AS_PAD] = (float(*)[AS_PAD])sm;                 // [64 k][256 row]
    float (*Ws)[WS_PAD] = (float(*)[WS_PAD])(sm + 64 * AS_PAD); // [64 k][64 col]
    const int t = threadIdx.x;
    const int block_row = blockIdx.x * GEMM_MTILE;
    const float4* A4 = src_sel ? (const float4*)d_h : (const float4*)A_ext;

    #pragma unroll
    for (int r = 0; r < 4; r++) {
        int p = t + r * 256;
        int k = p >> 4;
        int c4 = p & 15;
        float4 w = ((const float4*)W)[p];
        *(float4*)&Ws[k][c4 * 4] = w;
    }
    #pragma unroll
    for (int r = 0; r < 16; r++) {
        int p = t + r * 256;
        int row = p >> 4;
        int k4 = p & 15;
        int grow = block_row + row;
        float4 a = (grow < M) ? A4[grow * 16 + k4]
                              : make_float4(0.f, 0.f, 0.f, 0.f);
        As[k4 * 4 + 0][row] = a.x;
        As[k4 * 4 + 1][row] = a.y;
        As[k4 * 4 + 2][row] = a.z;
        As[k4 * 4 + 3][row] = a.w;
    }
    __syncthreads();

    const int tx = t & 7;    // col group (8 cols)
    const int ty = t >> 3;   // row group (32 groups x 8 rows)
    float acc[8][8] = {};
    #pragma unroll
    for (int k = 0; k < 64; k++) {
        float av[8], bv[8];
        *(float4*)&av[0] = *(const float4*)&As[k][ty * 8 + 0];
        *(float4*)&av[4] = *(const float4*)&As[k][ty * 8 + 4];
        *(float4*)&bv[0] = *(const float4*)&Ws[k][tx * 8 + 0];
        *(float4*)&bv[4] = *(const float4*)&Ws[k][tx * 8 + 4];
        #pragma unroll
        for (int i = 0; i < 8; i++)
            #pragma unroll
            for (int j = 0; j < 8; j++)
                acc[i][j] += av[i] * bv[j];
    }
    #pragma unroll
    for (int i = 0; i < 8; i++) {
        int grow = block_row + ty * 8 + i;
        if (grow < M) {
            float sc = d_dinv[grow];
            __half2 h0 = __floats2half2_rn(acc[i][0] * sc, acc[i][1] * sc);
            __half2 h1 = __floats2half2_rn(acc[i][2] * sc, acc[i][3] * sc);
            __half2 h2 = __floats2half2_rn(acc[i][4] * sc, acc[i][5] * sc);
            __half2 h3 = __floats2half2_rn(acc[i][6] * sc, acc[i][7] * sc);
            uint4 u;
            u.x = *(unsigned int*)&h0;
            u.y = *(unsigned int*)&h1;
            u.z = *(unsigned int*)&h2;
            u.w = *(unsigned int*)&h3;
            d_gh[grow * 8 + tx] = u;
        }
    }
}

__device__ __forceinline__ void acc8(uint4 v, float* a) {
    float2 f0 = __half22float2(*(__half2*)&v.x);
    float2 f1 = __half22float2(*(__half2*)&v.y);
    float2 f2 = __half22float2(*(__half2*)&v.z);
    float2 f3 = __half22float2(*(__half2*)&v.w);
    a[0] += f0.x; a[1] += f0.y; a[2] += f1.x; a[3] += f1.y;
    a[4] += f2.x; a[5] += f2.y; a[6] += f3.x; a[7] += f3.y;
}

// fused aggregation + epilogue: 8 threads per dst node, fp16 gather-reduce,
// out[d] = [relu]( dinv[d] * (sum_{e: dst=d} g[src_e] + g[d]) + b )
// dst_sel: 1 -> write d_h (fp32) + relu ; 0 -> write external out + zero deg
__global__ void k_gat(const float* __restrict__ b, float4* __restrict__ out_ext,
                      int dst_sel) {
    const uint4* __restrict__ g   = d_gh;
    const int*   __restrict__ srt = d_srcSorted;

    int t = blockIdx.x * blockDim.x + threadIdx.x;
    int node = t >> 3;
    if (node >= N_NODES) return;
    int c = t & 7;                          // 8 halves (16B) per thread

    float acc[8] = {};
    acc8(g[node * 8 + c], acc);             // self loop (already dinv-scaled)
    int start = d_rowstart[node];
    int cnt = d_deg[node];

    int j = 0;
    for (; j + 4 <= cnt; j += 4) {          // 4-wide: batch loads for MLP
        int s0 = srt[start + j + 0];
        int s1 = srt[start + j + 1];
        int s2 = srt[start + j + 2];
        int s3 = srt[start + j + 3];
        uint4 v0 = g[s0 * 8 + c];
        uint4 v1 = g[s1 * 8 + c];
        uint4 v2 = g[s2 * 8 + c];
        uint4 v3 = g[s3 * 8 + c];
        acc8(v0, acc); acc8(v1, acc); acc8(v2, acc); acc8(v3, acc);
    }
    for (; j < cnt; j++) {
        int si = srt[start + j];
        acc8(g[si * 8 + c], acc);
    }

    float dv = d_dinv[node];
    float4 b0 = ((const float4*)b)[c * 2 + 0];
    float4 b1 = ((const float4*)b)[c * 2 + 1];
    float4 o0, o1;
    o0.x = fmaf(dv, acc[0], b0.x); o0.y = fmaf(dv, acc[1], b0.y);
    o0.z = fmaf(dv, acc[2], b0.z); o0.w = fmaf(dv, acc[3], b0.w);
    o1.x = fmaf(dv, acc[4], b1.x); o1.y = fmaf(dv, acc[5], b1.y);
    o1.z = fmaf(dv, acc[6], b1.z); o1.w = fmaf(dv, acc[7], b1.w);
    if (dst_sel) {
        o0.x = fmaxf(o0.x, 0.f); o0.y = fmaxf(o0.y, 0.f);
        o0.z = fmaxf(o0.z, 0.f); o0.w = fmaxf(o0.w, 0.f);
        o1.x = fmaxf(o1.x, 0.f); o1.y = fmaxf(o1.y, 0.f);
        o1.z = fmaxf(o1.z, 0.f); o1.w = fmaxf(o1.w, 0.f);
        d_h[node * 16 + c * 2 + 0] = o0;
        d_h[node * 16 + c * 2 + 1] = o1;
    } else {
        out_ext[node * 16 + c * 2 + 0] = o0;
        out_ext[node * 16 + c * 2 + 1] = o1;
        if (c == 0) d_deg[node] = 0;        // re-zero for the next replay
    }
}

extern "C" void kernel_launch(void* const* d_in, const int* in_sizes, int n_in,
                              void* d_out, int out_size) {
    const float* x  = (const float*)d_in[0];
    const int*   ei = (const int*)d_in[1];     // int32 view; int64 handled per-block
    const float* W1 = (const float*)d_in[2];
    const float* b1 = (const float*)d_in[3];
    const float* W2 = (const float*)d_in[4];
    const float* b2 = (const float*)d_in[5];
    const int E = in_sizes[1] / 2;             // elements of edge_index / 2

    cudaFuncSetAttribute(k_gemm, cudaFuncAttributeMaxDynamicSharedMemorySize,
                         GEMM_SMEM);

    const int TPB = 256;
    const int gridE    = (E + TPB - 1) / TPB;
    const int gridGat  = (N_NODES * 8 + TPB - 1) / TPB;          // 3125
    const int gridGemm = (N_NODES + GEMM_MTILE - 1) / GEMM_MTILE; // 391

    // ---- CSR build (per run; deg is zero on entry) ----
    k_edge<<<gridE, TPB>>>(ei, E);
    k_scan1<<<NCHUNK, 256>>>();
    k_scan23<<<NCHUNK, 256>>>();
    k_scatter<<<gridE, TPB>>>(ei, E);

    // ---- layer 1 (GEMM1 strictly after scan23: epilogue reads d_dinv) ----
    k_gemm<<<gridGemm, TPB, GEMM_SMEM>>>(x, W1, N_NODES, 0);
    k_gat<<<gridGat, TPB>>>(b1, nullptr, 1);

    // ---- layer 2 ----
    k_gemm<<<gridGemm, TPB, GEMM_SMEM>>>(nullptr, W2, N_NODES, 1);
    k_gat<<<gridGat, TPB>>>(b2, (float4*)d_out, 0);
}

// round 13
// speedup vs baseline: 1.0591x; 1.0061x over previous
#include <cuda_runtime.h>
#include <cuda_fp16.h>

#define N_NODES 100000
#define MAX_E   1600000
#define FDIM    64
#define NCHUNK  ((N_NODES + 255) / 256)      // 391 scan chunks

#define GEMM_MTILE 256
#define AS_PAD     260                       // 256 rows + 4 pad
#define WS_PAD     68                        // 64 cols + 4 pad
#define GEMM_SMEM  ((64 * AS_PAD + 64 * WS_PAD) * 4)   // 83968 B

// ---- scratch (device globals referenced directly by kernels) ----
// d_deg is zero at module load and re-zeroed by layer-2 k_gat each run, so
// every graph replay sees a clean state without a dedicated init kernel.
__device__ int    d_deg[N_NODES];            // in-degree (real edges only)
__device__ int    d_rowstart[N_NODES];       // CSR row offsets (exclusive scan)
__device__ float  d_dinv[N_NODES];           // (1+deg)^{-1/2}
__device__ int    d_es[MAX_E];               // per-edge src
__device__ int2   d_dl[MAX_E];               // per-edge (dst, loc-in-bucket)
__device__ int    d_srcSorted[MAX_E];        // src indices grouped by dst
__device__ int    d_chunksum[512];           // per-chunk scan sums
__device__ uint4  d_gh[N_NODES * 8];         // dinv-scaled linear output, fp16 (128B/row)
__device__ float4 d_h[N_NODES * (FDIM / 4)]; // hidden activations (fp32)

// per-block edge dtype probe: int64 LE values < 2^32 have all odd int32 words
// zero over the first 512 words; int32 node ids make that vanishingly unlikely.
__device__ __forceinline__ int probe_mode64(const int* __restrict__ ei) {
    int t = threadIdx.x;
    int v = (t < 256) ? ei[2 * t + 1] : 0;
    return !__syncthreads_or(v != 0);        // 1 = int64, 0 = int32
}

__device__ __forceinline__ void decode_edge(const int* __restrict__ ei, int E,
                                            int mode64, int e, int& s, int& d) {
    if (mode64) { s = ei[2 * e]; d = ei[2 * (E + e)]; }
    else        { s = ei[e];     d = ei[E + e]; }
    if ((unsigned)s >= (unsigned)N_NODES) s = 0;   // safety clamp
    if ((unsigned)d >= (unsigned)N_NODES) d = 0;
}

// decode once: count in-degree AND capture each edge's offset in its bucket
__global__ void k_edge(const int* __restrict__ ei, int E) {
    int mode64 = probe_mode64(ei);
    int e = blockIdx.x * blockDim.x + threadIdx.x;
    if (e >= E) return;
    int s, d;
    decode_edge(ei, E, mode64, e, s, d);
    int loc = atomicAdd(&d_deg[d], 1);       // position within dst bucket
    d_es[e] = s;
    d_dl[e] = make_int2(d, loc);
}

// phase 1: per-256-chunk exclusive scan of deg (warp-shuffle), chunk totals out
__global__ void k_scan1() {
    __shared__ int wsum[8];
    int i = threadIdx.x;
    int gi = blockIdx.x * 256 + i;
    int v = (gi < N_NODES) ? d_deg[gi] : 0;
    int lane = i & 31, w = i >> 5;
    int x = v;
    #pragma unroll
    for (int off = 1; off < 32; off <<= 1) {
        int t = __shfl_up_sync(0xffffffffu, x, off);
        if (lane >= off) x += t;
    }
    if (lane == 31) wsum[w] = x;
    __syncthreads();
    if (w == 0) {
        int s = (lane < 8) ? wsum[lane] : 0;
        #pragma unroll
        for (int off = 1; off < 8; off <<= 1) {
            int t = __shfl_up_sync(0xffffffffu, s, off);
            if (lane >= off) s += t;
        }
        if (lane < 8) wsum[lane] = s;
    }
    __syncthreads();
    int excl = x - v + (w > 0 ? wsum[w - 1] : 0);
    if (gi < N_NODES) d_rowstart[gi] = excl;
    if (i == 255) d_chunksum[blockIdx.x] = wsum[7];
}

// fused phases 2+3: each block reduces chunksums below it (L2-hot, <=391 ints),
// then finalizes rowstart and dinv for its 256 nodes
__global__ void k_scan23() {
    __shared__ int red[256];
    int b = blockIdx.x;
    int t = threadIdx.x;
    int partial = 0;
    for (int i = t; i < b; i += 256) partial += d_chunksum[i];
    red[t] = partial;
    __syncthreads();
    #pragma unroll
    for (int off = 128; off > 0; off >>= 1) {
        if (t < off) red[t] += red[t + off];
        __syncthreads();
    }
    int base = red[0];
    int gi = b * 256 + t;
    if (gi < N_NODES) {
        d_rowstart[gi] += base;
        d_dinv[gi] = rsqrtf(1.0f + (float)d_deg[gi]);
    }
}

// atomic-free scatter: pos = rowstart[dst] + loc (captured in k_edge)
__global__ void k_scatter(int E) {
    int e = blockIdx.x * blockDim.x + threadIdx.x;
    if (e >= E) return;
    int2 dl = d_dl[e];
    d_srcSorted[d_rowstart[dl.x] + dl.y] = d_es[e];
}

// g[row] = fp16( (A[row] @ W) * dinv[row] );  M x 64 @ 64 x 64
// 256 threads, 256x64 tile, 8x8 register tile
__global__ __launch_bounds__(256) void k_gemm(
    const float* __restrict__ A_ext, const float* __restrict__ W,
    int M, int src_sel) {
    extern __shared__ float sm[];
    float (*As)[AS_PAD] = (float(*)[AS_PAD])sm;                 // [64 k][256 row]
    float (*Ws)[WS_PAD] = (float(*)[WS_PAD])(sm + 64 * AS_PAD); // [64 k][64 col]
    const int t = threadIdx.x;
    const int block_row = blockIdx.x * GEMM_MTILE;
    const float4* A4 = src_sel ? (const float4*)d_h : (const float4*)A_ext;

    #pragma unroll
    for (int r = 0; r < 4; r++) {
        int p = t + r * 256;
        int k = p >> 4;
        int c4 = p & 15;
        float4 w = ((const float4*)W)[p];
        *(float4*)&Ws[k][c4 * 4] = w;
    }
    #pragma unroll
    for (int r = 0; r < 16; r++) {
        int p = t + r * 256;
        int row = p >> 4;
        int k4 = p & 15;
        int grow = block_row + row;
        float4 a = (grow < M) ? A4[grow * 16 + k4]
                              : make_float4(0.f, 0.f, 0.f, 0.f);
        As[k4 * 4 + 0][row] = a.x;
        As[k4 * 4 + 1][row] = a.y;
        As[k4 * 4 + 2][row] = a.z;
        As[k4 * 4 + 3][row] = a.w;
    }
    __syncthreads();

    const int tx = t & 7;    // col group (8 cols)
    const int ty = t >> 3;   // row group (32 groups x 8 rows)
    float acc[8][8] = {};
    #pragma unroll
    for (int k = 0; k < 64; k++) {
        float av[8], bv[8];
        *(float4*)&av[0] = *(const float4*)&As[k][ty * 8 + 0];
        *(float4*)&av[4] = *(const float4*)&As[k][ty * 8 + 4];
        *(float4*)&bv[0] = *(const float4*)&Ws[k][tx * 8 + 0];
        *(float4*)&bv[4] = *(const float4*)&Ws[k][tx * 8 + 4];
        #pragma unroll
        for (int i = 0; i < 8; i++)
            #pragma unroll
            for (int j = 0; j < 8; j++)
                acc[i][j] += av[i] * bv[j];
    }
    #pragma unroll
    for (int i = 0; i < 8; i++) {
        int grow = block_row + ty * 8 + i;
        if (grow < M) {
            float sc = d_dinv[grow];
            __half2 h0 = __floats2half2_rn(acc[i][0] * sc, acc[i][1] * sc);
            __half2 h1 = __floats2half2_rn(acc[i][2] * sc, acc[i][3] * sc);
            __half2 h2 = __floats2half2_rn(acc[i][4] * sc, acc[i][5] * sc);
            __half2 h3 = __floats2half2_rn(acc[i][6] * sc, acc[i][7] * sc);
            uint4 u;
            u.x = *(unsigned int*)&h0;
            u.y = *(unsigned int*)&h1;
            u.z = *(unsigned int*)&h2;
            u.w = *(unsigned int*)&h3;
            d_gh[grow * 8 + tx] = u;
        }
    }
}

__device__ __forceinline__ void acc8(uint4 v, float* a) {
    float2 f0 = __half22float2(*(__half2*)&v.x);
    float2 f1 = __half22float2(*(__half2*)&v.y);
    float2 f2 = __half22float2(*(__half2*)&v.z);
    float2 f3 = __half22float2(*(__half2*)&v.w);
    a[0] += f0.x; a[1] += f0.y; a[2] += f1.x; a[3] += f1.y;
    a[4] += f2.x; a[5] += f2.y; a[6] += f3.x; a[7] += f3.y;
}

// fused aggregation + epilogue: 8 threads per dst node, fp16 gather-reduce,
// out[d] = [relu]( dinv[d] * (sum_{e: dst=d} g[src_e] + g[d]) + b )
// dst_sel: 1 -> write d_h (fp32) + relu ; 0 -> write external out + zero deg
__global__ void k_gat(const float* __restrict__ b, float4* __restrict__ out_ext,
                      int dst_sel) {
    const uint4* __restrict__ g   = d_gh;
    const int*   __restrict__ srt = d_srcSorted;

    int t = blockIdx.x * blockDim.x + threadIdx.x;
    int node = t >> 3;
    if (node >= N_NODES) return;
    int c = t & 7;                          // 8 halves (16B) per thread

    float acc[8] = {};
    acc8(g[node * 8 + c], acc);             // self loop (already dinv-scaled)
    int start = d_rowstart[node];
    int cnt = d_deg[node];

    int j = 0;
    for (; j + 4 <= cnt; j += 4) {          // 4-wide: batch loads for MLP
        int s0 = srt[start + j + 0];
        int s1 = srt[start + j + 1];
        int s2 = srt[start + j + 2];
        int s3 = srt[start + j + 3];
        uint4 v0 = g[s0 * 8 + c];
        uint4 v1 = g[s1 * 8 + c];
        uint4 v2 = g[s2 * 8 + c];
        uint4 v3 = g[s3 * 8 + c];
        acc8(v0, acc); acc8(v1, acc); acc8(v2, acc); acc8(v3, acc);
    }
    for (; j < cnt; j++) {
        int si = srt[start + j];
        acc8(g[si * 8 + c], acc);
    }

    float dv = d_dinv[node];
    float4 b0 = ((const float4*)b)[c * 2 + 0];
    float4 b1 = ((const float4*)b)[c * 2 + 1];
    float4 o0, o1;
    o0.x = fmaf(dv, acc[0], b0.x); o0.y = fmaf(dv, acc[1], b0.y);
    o0.z = fmaf(dv, acc[2], b0.z); o0.w = fmaf(dv, acc[3], b0.w);
    o1.x = fmaf(dv, acc[4], b1.x); o1.y = fmaf(dv, acc[5], b1.y);
    o1.z = fmaf(dv, acc[6], b1.z); o1.w = fmaf(dv, acc[7], b1.w);
    if (dst_sel) {
        o0.x = fmaxf(o0.x, 0.f); o0.y = fmaxf(o0.y, 0.f);
        o0.z = fmaxf(o0.z, 0.f); o0.w = fmaxf(o0.w, 0.f);
        o1.x = fmaxf(o1.x, 0.f); o1.y = fmaxf(o1.y, 0.f);
        o1.z = fmaxf(o1.z, 0.f); o1.w = fmaxf(o1.w, 0.f);
        d_h[node * 16 + c * 2 + 0] = o0;
        d_h[node * 16 + c * 2 + 1] = o1;
    } else {
        out_ext[node * 16 + c * 2 + 0] = o0;
        out_ext[node * 16 + c * 2 + 1] = o1;
        if (c == 0) d_deg[node] = 0;        // re-zero for the next replay
    }
}

extern "C" void kernel_launch(void* const* d_in, const int* in_sizes, int n_in,
                              void* d_out, int out_size) {
    const float* x  = (const float*)d_in[0];
    const int*   ei = (const int*)d_in[1];     // int32 view; int64 handled per-block
    const float* W1 = (const float*)d_in[2];
    const float* b1 = (const float*)d_in[3];
    const float* W2 = (const float*)d_in[4];
    const float* b2 = (const float*)d_in[5];
    const int E = in_sizes[1] / 2;             // elements of edge_index / 2

    cudaFuncSetAttribute(k_gemm, cudaFuncAttributeMaxDynamicSharedMemorySize,
                         GEMM_SMEM);

    const int TPB = 256;
    const int gridE    = (E + TPB - 1) / TPB;
    const int gridGat  = (N_NODES * 8 + TPB - 1) / TPB;          // 3125
    const int gridGemm = (N_NODES + GEMM_MTILE - 1) / GEMM_MTILE; // 391

    // ---- CSR build (per run; deg is zero on entry) ----
    k_edge<<<gridE, TPB>>>(ei, E);
    k_scan1<<<NCHUNK, 256>>>();
    k_scan23<<<NCHUNK, 256>>>();
    k_scatter<<<gridE, TPB>>>(E);

    // ---- layer 1 (GEMM1 strictly after scan23: epilogue reads d_dinv) ----
    k_gemm<<<gridGemm, TPB, GEMM_SMEM>>>(x, W1, N_NODES, 0);
    k_gat<<<gridGat, TPB>>>(b1, nullptr, 1);

    // ---- layer 2 ----
    k_gemm<<<gridGemm, TPB, GEMM_SMEM>>>(nullptr, W2, N_NODES, 1);
    k_gat<<<gridGat, TPB>>>(b2, (float4*)d_out, 0);
}

// round 14
// speedup vs baseline: 1.1234x; 1.0607x over previous
#include <cuda_runtime.h>
#include <cuda_fp16.h>

#define N_NODES 100000
#define MAX_E   1600000
#define FDIM    64
#define NCHUNK  ((N_NODES + 255) / 256)      // 391 scan chunks

#define GEMM_MTILE 256
#define AS_PAD     260                       // 256 rows + 4 pad
#define WS_PAD     68                        // 64 cols + 4 pad
#define GEMM_SMEM  ((64 * AS_PAD + 64 * WS_PAD) * 4)   // 83968 B

// ---- scratch (device globals referenced directly by kernels) ----
// d_deg and d_state are zero at module load and re-zeroed by layer-2 k_gat
// each run, so every replay sees a clean state without an init kernel.
__device__ int                d_deg[N_NODES];      // in-degree (real edges)
__device__ int                d_rowstart[N_NODES]; // CSR row offsets
__device__ float              d_dinv[N_NODES];     // (1+deg)^{-1/2}
__device__ int                d_es[MAX_E];         // per-edge src
__device__ unsigned int       d_pack[MAX_E];       // per-edge dst | (loc<<17)
__device__ int                d_srcSorted[MAX_E];  // src grouped by dst
__device__ unsigned long long d_state[512];        // lookback: flag<<32 | value
__device__ uint4              d_gh[N_NODES * 8];   // layer input g, fp16 (128B/row)
__device__ uint4              d_hh[N_NODES * 8];   // hidden h, fp16 (128B/row)

// per-block edge dtype probe: int64 LE values < 2^32 have all odd int32 words
// zero over the first 512 words; int32 node ids make that vanishingly unlikely.
__device__ __forceinline__ int probe_mode64(const int* __restrict__ ei) {
    int t = threadIdx.x;
    int v = (t < 256) ? ei[2 * t + 1] : 0;
    return !__syncthreads_or(v != 0);        // 1 = int64, 0 = int32
}

// decode once: count in-degree AND capture each edge's offset in its bucket
__global__ void k_edge(const int* __restrict__ ei, int E) {
    int mode64 = probe_mode64(ei);
    int e = blockIdx.x * blockDim.x + threadIdx.x;
    if (e >= E) return;
    int s, d;
    if (mode64) { s = ei[2 * e]; d = ei[2 * (E + e)]; }
    else        { s = ei[e];     d = ei[E + e]; }
    if ((unsigned)s >= (unsigned)N_NODES) s = 0;   // safety clamp
    if ((unsigned)d >= (unsigned)N_NODES) d = 0;
    unsigned loc = (unsigned)atomicAdd(&d_deg[d], 1);  // pos within dst bucket
    d_es[e] = s;
    d_pack[e] = (unsigned)d | (loc << 17);
}

// single-pass scan (decoupled lookback): per-256 chunk exclusive scan of deg,
// cross-chunk prefix via 64-bit flag|value words, then finalize rowstart+dinv.
__global__ void k_scan() {
    __shared__ int wsum[8];
    __shared__ int sbase;
    int b = blockIdx.x;
    int i = threadIdx.x;
    int gi = b * 256 + i;
    int v = (gi < N_NODES) ? d_deg[gi] : 0;
    int lane = i & 31, w = i >> 5;
    int x = v;
    #pragma unroll
    for (int off = 1; off < 32; off <<= 1) {
        int t = __shfl_up_sync(0xffffffffu, x, off);
        if (lane >= off) x += t;
    }
    if (lane == 31) wsum[w] = x;
    __syncthreads();
    if (w == 0) {
        int s = (lane < 8) ? wsum[lane] : 0;
        #pragma unroll
        for (int off = 1; off < 8; off <<= 1) {
            int t = __shfl_up_sync(0xffffffffu, s, off);
            if (lane >= off) s += t;
        }
        if (lane < 8) wsum[lane] = s;
    }
    __syncthreads();
    int excl = x - v + (w > 0 ? wsum[w - 1] : 0);
    int total = wsum[7];

    if (w == 0) {
        if (b == 0) {
            if (lane == 0) {
                *(volatile unsigned long long*)&d_state[0] =
                    (2ULL << 32) | (unsigned)total;
                sbase = 0;
            }
        } else {
            if (lane == 0)
                *(volatile unsigned long long*)&d_state[b] =
                    (1ULL << 32) | (unsigned)total;
            int running = 0;
            int idx = b - 1 - lane;           // warp-windowed lookback
            bool done = false;
            while (!done) {
                unsigned long long st = (idx >= 0)
                    ? *(volatile unsigned long long*)&d_state[idx]
                    : (2ULL << 32);
                unsigned f = (unsigned)(st >> 32);
                if (__all_sync(0xffffffffu, f >= 1)) {
                    unsigned mask = __ballot_sync(0xffffffffu, f == 2);
                    int firstPref = mask ? (__ffs(mask) - 1) : 32;
                    int contrib = (lane <= firstPref)
                                  ? (int)(unsigned)(st & 0xffffffffu) : 0;
                    #pragma unroll
                    for (int off = 16; off; off >>= 1)
                        contrib += __shfl_down_sync(0xffffffffu, contrib, off);
                    if (lane == 0) running += contrib;
                    if (mask) done = true;
                    else idx -= 32;
                }
            }
            if (lane == 0) {
                *(volatile unsigned long long*)&d_state[b] =
                    (2ULL << 32) | (unsigned)(running + total);
                sbase = running;
            }
        }
    }
    __syncthreads();
    int base = sbase;
    if (gi < N_NODES) {
        d_rowstart[gi] = excl + base;
        d_dinv[gi] = rsqrtf(1.0f + (float)v);
    }
}

// atomic-free scatter: pos = rowstart[dst] + loc (captured in k_edge)
__global__ void k_scatter(int E) {
    int e = blockIdx.x * blockDim.x + threadIdx.x;
    if (e >= E) return;
    unsigned p = d_pack[e];
    int d = (int)(p & 0x1ffffu);
    int loc = (int)(p >> 17);
    d_srcSorted[d_rowstart[d] + loc] = d_es[e];
}

// g[row] = fp16( (A[row] @ W) * dinv[row] );  M x 64 @ 64 x 64
// 256 threads, 256x64 tile, 8x8 register tile
// src_sel: 0 -> A from harness fp32 pointer, 1 -> A from d_hh (fp16)
__global__ __launch_bounds__(256) void k_gemm(
    const float* __restrict__ A_ext, const float* __restrict__ W,
    int M, int src_sel) {
    extern __shared__ float sm[];
    float (*As)[AS_PAD] = (float(*)[AS_PAD])sm;                 // [64 k][256 row]
    float (*Ws)[WS_PAD] = (float(*)[WS_PAD])(sm + 64 * AS_PAD); // [64 k][64 col]
    const int t = threadIdx.x;
    const int block_row = blockIdx.x * GEMM_MTILE;

    #pragma unroll
    for (int r = 0; r < 4; r++) {
        int p = t + r * 256;
        int k = p >> 4;
        int c4 = p & 15;
        float4 w = ((const float4*)W)[p];
        *(float4*)&Ws[k][c4 * 4] = w;
    }
    #pragma unroll
    for (int r = 0; r < 16; r++) {
        int p = t + r * 256;
        int row = p >> 4;
        int k4 = p & 15;
        int grow = block_row + row;
        float4 a;
        if (grow >= M) {
            a = make_float4(0.f, 0.f, 0.f, 0.f);
        } else if (src_sel) {
            uint2 hv = ((const uint2*)d_hh)[grow * 16 + k4];
            float2 f0 = __half22float2(*(__half2*)&hv.x);
            float2 f1 = __half22float2(*(__half2*)&hv.y);
            a = make_float4(f0.x, f0.y, f1.x, f1.y);
        } else {
            a = ((const float4*)A_ext)[grow * 16 + k4];
        }
        As[k4 * 4 + 0][row] = a.x;
        As[k4 * 4 + 1][row] = a.y;
        As[k4 * 4 + 2][row] = a.z;
        As[k4 * 4 + 3][row] = a.w;
    }
    __syncthreads();

    const int tx = t & 7;    // col group (8 cols)
    const int ty = t >> 3;   // row group (32 groups x 8 rows)
    float acc[8][8] = {};
    #pragma unroll
    for (int k = 0; k < 64; k++) {
        float av[8], bv[8];
        *(float4*)&av[0] = *(const float4*)&As[k][ty * 8 + 0];
        *(float4*)&av[4] = *(const float4*)&As[k][ty * 8 + 4];
        *(float4*)&bv[0] = *(const float4*)&Ws[k][tx * 8 + 0];
        *(float4*)&bv[4] = *(const float4*)&Ws[k][tx * 8 + 4];
        #pragma unroll
        for (int i = 0; i < 8; i++)
            #pragma unroll
            for (int j = 0; j < 8; j++)
                acc[i][j] += av[i] * bv[j];
    }
    #pragma unroll
    for (int i = 0; i < 8; i++) {
        int grow = block_row + ty * 8 + i;
        if (grow < M) {
            float sc = d_dinv[grow];
            __half2 h0 = __floats2half2_rn(acc[i][0] * sc, acc[i][1] * sc);
            __half2 h1 = __floats2half2_rn(acc[i][2] * sc, acc[i][3] * sc);
            __half2 h2 = __floats2half2_rn(acc[i][4] * sc, acc[i][5] * sc);
            __half2 h3 = __floats2half2_rn(acc[i][6] * sc, acc[i][7] * sc);
            uint4 u;
            u.x = *(unsigned int*)&h0;
            u.y = *(unsigned int*)&h1;
            u.z = *(unsigned int*)&h2;
            u.w = *(unsigned int*)&h3;
            d_gh[grow * 8 + tx] = u;
        }
    }
}

__device__ __forceinline__ void acc8(uint4 v, float* a) {
    float2 f0 = __half22float2(*(__half2*)&v.x);
    float2 f1 = __half22float2(*(__half2*)&v.y);
    float2 f2 = __half22float2(*(__half2*)&v.z);
    float2 f3 = __half22float2(*(__half2*)&v.w);
    a[0] += f0.x; a[1] += f0.y; a[2] += f1.x; a[3] += f1.y;
    a[4] += f2.x; a[5] += f2.y; a[6] += f3.x; a[7] += f3.y;
}

// fused aggregation + epilogue: 8 threads per dst node, fp16 gather-reduce,
// out[d] = [relu]( dinv[d] * (sum_{e: dst=d} g[src_e] + g[d]) + b )
// dst_sel: 1 -> write d_hh (fp16) + relu ; 0 -> write external out + reset state
__global__ void k_gat(const float* __restrict__ b, float4* __restrict__ out_ext,
                      int dst_sel) {
    const uint4* __restrict__ g   = d_gh;
    const int*   __restrict__ srt = d_srcSorted;

    int t = blockIdx.x * blockDim.x + threadIdx.x;
    int node = t >> 3;
    if (node >= N_NODES) return;
    int c = t & 7;                          // 8 halves (16B) per thread

    float acc[8] = {};
    acc8(g[node * 8 + c], acc);             // self loop (already dinv-scaled)
    int start = d_rowstart[node];
    int cnt = d_deg[node];

    int j = 0;
    for (; j + 4 <= cnt; j += 4) {          // 4-wide: batch loads for MLP
        int s0 = srt[start + j + 0];
        int s1 = srt[start + j + 1];
        int s2 = srt[start + j + 2];
        int s3 = srt[start + j + 3];
        uint4 v0 = g[s0 * 8 + c];
        uint4 v1 = g[s1 * 8 + c];
        uint4 v2 = g[s2 * 8 + c];
        uint4 v3 = g[s3 * 8 + c];
        acc8(v0, acc); acc8(v1, acc); acc8(v2, acc); acc8(v3, acc);
    }
    for (; j < cnt; j++) {
        int si = srt[start + j];
        acc8(g[si * 8 + c], acc);
    }

    float dv = d_dinv[node];
    float4 b0 = ((const float4*)b)[c * 2 + 0];
    float4 b1 = ((const float4*)b)[c * 2 + 1];
    float4 o0, o1;
    o0.x = fmaf(dv, acc[0], b0.x); o0.y = fmaf(dv, acc[1], b0.y);
    o0.z = fmaf(dv, acc[2], b0.z); o0.w = fmaf(dv, acc[3], b0.w);
    o1.x = fmaf(dv, acc[4], b1.x); o1.y = fmaf(dv, acc[5], b1.y);
    o1.z = fmaf(dv, acc[6], b1.z); o1.w = fmaf(dv, acc[7], b1.w);
    if (dst_sel) {
        o0.x = fmaxf(o0.x, 0.f); o0.y = fmaxf(o0.y, 0.f);
        o0.z = fmaxf(o0.z, 0.f); o0.w = fmaxf(o0.w, 0.f);
        o1.x = fmaxf(o1.x, 0.f); o1.y = fmaxf(o1.y, 0.f);
        o1.z = fmaxf(o1.z, 0.f); o1.w = fmaxf(o1.w, 0.f);
        __half2 q0 = __floats2half2_rn(o0.x, o0.y);
        __half2 q1 = __floats2half2_rn(o0.z, o0.w);
        __half2 q2 = __floats2half2_rn(o1.x, o1.y);
        __half2 q3 = __floats2half2_rn(o1.z, o1.w);
        uint4 u;
        u.x = *(unsigned int*)&q0;
        u.y = *(unsigned int*)&q1;
        u.z = *(unsigned int*)&q2;
        u.w = *(unsigned int*)&q3;
        d_hh[node * 8 + c] = u;
    } else {
        out_ext[node * 16 + c * 2 + 0] = o0;
        out_ext[node * 16 + c * 2 + 1] = o1;
        if (c == 0) d_deg[node] = 0;            // reset for the next replay
        if (c == 1 && node < NCHUNK) d_state[node] = 0ULL;
    }
}

extern "C" void kernel_launch(void* const* d_in, const int* in_sizes, int n_in,
                              void* d_out, int out_size) {
    const float* x  = (const float*)d_in[0];
    const int*   ei = (const int*)d_in[1];     // int32 view; int64 handled per-block
    const float* W1 = (const float*)d_in[2];
    const float* b1 = (const float*)d_in[3];
    const float* W2 = (const float*)d_in[4];
    const float* b2 = (const float*)d_in[5];
    const int E = in_sizes[1] / 2;             // elements of edge_index / 2

    cudaFuncSetAttribute(k_gemm, cudaFuncAttributeMaxDynamicSharedMemorySize,
                         GEMM_SMEM);

    const int TPB = 256;
    const int gridE    = (E + TPB - 1) / TPB;
    const int gridGat  = (N_NODES * 8 + TPB - 1) / TPB;          // 3125
    const int gridGemm = (N_NODES + GEMM_MTILE - 1) / GEMM_MTILE; // 391

    // ---- CSR build (per run; deg/state are zero on entry) ----
    k_edge<<<gridE, TPB>>>(ei, E);
    k_scan<<<NCHUNK, 256>>>();
    k_scatter<<<gridE, TPB>>>(E);

    // ---- layer 1 (GEMM1 strictly after k_scan: epilogue reads d_dinv) ----
    k_gemm<<<gridGemm, TPB, GEMM_SMEM>>>(x, W1, N_NODES, 0);
    k_gat<<<gridGat, TPB>>>(b1, nullptr, 1);

    // ---- layer 2 ----
    k_gemm<<<gridGemm, TPB, GEMM_SMEM>>>(nullptr, W2, N_NODES, 1);
    k_gat<<<gridGat, TPB>>>(b2, (float4*)d_out, 0);
}